// round 16
// baseline (speedup 1.0000x reference)
#include <cuda_runtime.h>
#include <cuda_bf16.h>
#include <math.h>
#include <stdint.h>

#define NN 30000
#define EE 240000
#define DM 256
#define NH 4
#define HD 64
#define NG 64
#define NL 3

// ---------------- scratch (static device globals; no allocs) ----------------
__device__ float g_qf[NN * DM];       // q in fp32
__device__ float g_gsum[NG * DM];
__device__ float g_cnt[NG];
__device__ int g_total;
// bf16 operands / activations
__device__ __nv_bfloat16 g_kb[NN * DM];
__device__ __nv_bfloat16 g_vb[NN * DM];
__device__ __nv_bfloat16 g_xhi[NN * DM];
__device__ __nv_bfloat16 g_xlo[NN * DM];
__device__ __nv_bfloat16 g_whi[9 * DM * DM];  // [l*3+mat][n][k] K-major
__device__ __nv_bfloat16 g_wlo[9 * DM * DM];
// CSR by destination node (offsets NOT monotone in n; segment = [off, off+cnt))
__device__ int g_ccnt[NN];
__device__ int g_coff[NN];
__device__ int g_ccur[NN];
__device__ int g_cdat[EE];            // src | (et << 16)

// ---------------- helpers ----------------
__device__ __forceinline__ void red_add_v4(float* p, float4 v) {
    asm volatile("red.global.add.v4.f32 [%0], {%1,%2,%3,%4};"
                 :: "l"(p), "f"(v.x), "f"(v.y), "f"(v.z), "f"(v.w) : "memory");
}
__device__ __forceinline__ uint32_t smem_u32(const void* p) {
    uint32_t a;
    asm("{ .reg .u64 t; cvta.to.shared.u64 t, %1; cvt.u32.u64 %0, t; }"
        : "=r"(a) : "l"(p));
    return a;
}

#define LDSM4(r, addr) \
    asm volatile("ldmatrix.sync.aligned.m8n8.x4.shared.b16 {%0,%1,%2,%3}, [%4];" \
                 : "=r"((r)[0]), "=r"((r)[1]), "=r"((r)[2]), "=r"((r)[3]) \
                 : "r"(addr))

#define MMA16816(c, a, b0, b1) \
    asm volatile("mma.sync.aligned.m16n8k16.row.col.f32.bf16.bf16.f32 " \
                 "{%0,%1,%2,%3},{%4,%5,%6,%7},{%8,%9},{%0,%1,%2,%3};" \
                 : "+f"((c)[0]), "+f"((c)[1]), "+f"((c)[2]), "+f"((c)[3]) \
                 : "r"((a)[0]), "r"((a)[1]), "r"((a)[2]), "r"((a)[3]), \
                   "r"(b0), "r"(b1))

#define CP16(smaddr, gptr) \
    asm volatile("cp.async.ca.shared.global [%0], [%1], 16;" \
                 :: "r"(smaddr), "l"(gptr) : "memory")
#define CPCOMMIT() asm volatile("cp.async.commit_group;" ::: "memory")
#define CPWAIT1() asm volatile("cp.async.wait_group 1;" ::: "memory")
#define CPWAIT0() asm volatile("cp.async.wait_group 0;" ::: "memory")

__device__ __forceinline__ void split_bf16(float v, unsigned short& h, unsigned short& l) {
    __nv_bfloat16 hb = __float2bfloat16(v);
    h = __bfloat16_as_ushort(hb);
    l = __bfloat16_as_ushort(__float2bfloat16(v - __bfloat162float(hb)));
}

// ---------------- zero all small buffers in one launch ----------------
__global__ __launch_bounds__(256) void zero_bufs()
{
    int i = blockIdx.x * blockDim.x + threadIdx.x;
    if (i < NN) g_ccnt[i] = 0;
    if (i < NG * DM) g_gsum[i] = 0.f;
    if (i < NG) g_cnt[i] = 0.f;
    if (i == 0) g_total = 0;
}

// ---------------- CSR construction ----------------
__global__ __launch_bounds__(256) void csr_hist(const int* __restrict__ dst)
{
    int e = blockIdx.x * blockDim.x + threadIdx.x;
    if (e < EE) atomicAdd(&g_ccnt[dst[e]], 1);
}

__global__ __launch_bounds__(256) void csr_off()
{
    int n = blockIdx.x * blockDim.x + threadIdx.x;
    if (n >= NN) return;
    int c = g_ccnt[n];
    int p = atomicAdd(&g_total, c);
    g_coff[n] = p;
    g_ccur[n] = p;
}

__global__ __launch_bounds__(256) void csr_scatter(
    const int* __restrict__ src, const int* __restrict__ dst,
    const int* __restrict__ et)
{
    int e = blockIdx.x * blockDim.x + threadIdx.x;
    if (e >= EE) return;
    int p = atomicAdd(&g_ccur[dst[e]], 1);
    g_cdat[p] = src[e] | (et[e] << 16);
}

// ---------------- bf16 split conversion: x -> hi/lo (layer 0 only) ----------
__global__ __launch_bounds__(256) void conv_x(
    const float* __restrict__ x, __nv_bfloat16* __restrict__ hi,
    __nv_bfloat16* __restrict__ lo)
{
    int i = blockIdx.x * blockDim.x + threadIdx.x;
    if (i >= NN * DM / 8) return;
    const float4* x4 = (const float4*)x;
    float4 a = x4[2 * i], b = x4[2 * i + 1];
    float v[8] = {a.x, a.y, a.z, a.w, b.x, b.y, b.z, b.w};
    unsigned short hb[8], lb[8];
#pragma unroll
    for (int j = 0; j < 8; j++) split_bf16(v[j], hb[j], lb[j]);
    uint4 ho, lu;
    ho.x = hb[0] | ((uint32_t)hb[1] << 16); ho.y = hb[2] | ((uint32_t)hb[3] << 16);
    ho.z = hb[4] | ((uint32_t)hb[5] << 16); ho.w = hb[6] | ((uint32_t)hb[7] << 16);
    lu.x = lb[0] | ((uint32_t)lb[1] << 16); lu.y = lb[2] | ((uint32_t)lb[3] << 16);
    lu.z = lb[4] | ((uint32_t)lb[5] << 16); lu.w = lb[6] | ((uint32_t)lb[7] << 16);
    ((uint4*)hi)[i] = ho;
    ((uint4*)lo)[i] = lu;
}

// ---------------- W transpose + split ----------------
__global__ void conv_w(const float* __restrict__ Wq, const float* __restrict__ Wk,
                       const float* __restrict__ Wv,
                       __nv_bfloat16* __restrict__ whi, __nv_bfloat16* __restrict__ wlo)
{
    __shared__ float t[32][33];
    int m3 = blockIdx.z, l = m3 / 3, mat = m3 % 3;
    const float* W = ((mat == 0) ? Wq : (mat == 1) ? Wk : Wv) + (size_t)l * DM * DM;
    int n0 = blockIdx.x * 32, k0 = blockIdx.y * 32;
#pragma unroll
    for (int i = 0; i < 4; i++)
        t[threadIdx.y + i * 8][threadIdx.x] =
            W[(size_t)(k0 + threadIdx.y + i * 8) * DM + n0 + threadIdx.x];
    __syncthreads();
#pragma unroll
    for (int i = 0; i < 4; i++) {
        int n = n0 + threadIdx.y + i * 8;
        int k = k0 + threadIdx.x;
        float v = t[threadIdx.x][threadIdx.y + i * 8];
        unsigned short h, lo16;
        split_bf16(v, h, lo16);
        size_t o = (size_t)m3 * DM * DM + (size_t)n * DM + k;
        whi[o] = __ushort_as_bfloat16(h);
        wlo[o] = __ushort_as_bfloat16(lo16);
    }
}

// ---------------- HMMA split GEMM, cp.async 2-stage (R10 config) -------------
// grid (6, 235). 512 threads. CTA tile 128x128, K=256 in 4 chunks of 64.
// Full 3-term split everywhere (R11 lesson: bf16-rounded weights = systematic
// error). This exact config (1 CTA/SM, 2-stage) beat 3-stage and 2-CTA/SM
// variants in R12-R14 A/B tests — do not restructure without profile evidence.
__global__ __launch_bounds__(512, 1) void gemm_tc(
    const __nv_bfloat16* __restrict__ xhi, const __nv_bfloat16* __restrict__ xlo,
    const __nv_bfloat16* __restrict__ whi, const __nv_bfloat16* __restrict__ wlo,
    const float* __restrict__ bq, const float* __restrict__ bk,
    const float* __restrict__ bv,
    float* __restrict__ Cq, __nv_bfloat16* __restrict__ Ck,
    __nv_bfloat16* __restrict__ Cv)
{
    extern __shared__ char sm[];
    __shared__ float s_bias[128];
    const uint32_t sbase = smem_u32(sm);
    const uint32_t AH = 0, AL = 16384, BH = 32768, BL = 49152;
    const uint32_t STAGE = 65536;

    const int tid = threadIdx.x;
    const int warp = tid >> 5, lane = tid & 31;
    const int wm = warp & 3, wn = warp >> 2;
    const int mat = blockIdx.x >> 1;
    const int bcol = (blockIdx.x & 1) * 128;
    const int brow = blockIdx.y * 128;

    const float* bias = (mat == 0) ? bq : (mat == 1) ? bk : bv;
    if (tid < 128) s_bias[tid] = bias[bcol + tid];

    const int lrow = tid >> 2;
    const int lq = tid & 3;
    const int arow = min(brow + lrow, NN - 1);
    const __nv_bfloat16* pAh = xhi + (size_t)arow * DM;
    const __nv_bfloat16* pAl = xlo + (size_t)arow * DM;
    const __nv_bfloat16* pBh = whi + (size_t)mat * DM * DM + (size_t)(bcol + lrow) * DM;
    const __nv_bfloat16* pBl = wlo + (size_t)mat * DM * DM + (size_t)(bcol + lrow) * DM;
    const int lrx = lrow & 7;

    const int sA_m = ((lane >> 3) & 1) * 8 + (lane & 7);
    const int sA_k = lane >> 4;
    const int sB_n = (lane >> 4) * 8 + (lane & 7);
    const int sB_k = (lane >> 3) & 1;
    const int rowA0 = wm * 32 + sA_m;
    const int rowB0 = wn * 32 + sB_n;
    const int rxA = sA_m & 7;
    const int rxB = sB_n & 7;

    float acc[2][4][4];
#pragma unroll
    for (int mt = 0; mt < 2; mt++)
#pragma unroll
        for (int nt = 0; nt < 4; nt++)
#pragma unroll
            for (int j = 0; j < 4; j++) acc[mt][nt][j] = 0.f;

#define ISSUE_CHUNK(chunk, stg)                                                  \
    {                                                                            \
        _Pragma("unroll")                                                        \
        for (int j = 0; j < 2; j++) {                                            \
            int g = lq + j * 4;                                                  \
            int elem = (chunk) * 64 + g * 8;                                     \
            uint32_t sw = (uint32_t)(lrow * 128 + ((g ^ lrx) << 4));             \
            CP16((stg) + AH + sw, pAh + elem);                                   \
            CP16((stg) + AL + sw, pAl + elem);                                   \
            CP16((stg) + BH + sw, pBh + elem);                                   \
            CP16((stg) + BL + sw, pBl + elem);                                   \
        }                                                                        \
        CPCOMMIT();                                                              \
    }

    ISSUE_CHUNK(0, sbase);

#pragma unroll
    for (int c = 0; c < 4; c++) {
        const uint32_t cb = sbase + (uint32_t)(c & 1) * STAGE;
        if (c < 3) {
            ISSUE_CHUNK(c + 1, sbase + (uint32_t)((c + 1) & 1) * STAGE);
            CPWAIT1();
        } else {
            CPWAIT0();
        }
        __syncthreads();

#pragma unroll
        for (int ks = 0; ks < 4; ks++) {
            const int kgA = ks * 2 + sA_k;
            const int kgB = ks * 2 + sB_k;
            uint32_t ah[2][4], al[2][4], bh[2][4], bl[2][4];
#pragma unroll
            for (int mt = 0; mt < 2; mt++) {
                uint32_t off = (uint32_t)((rowA0 + mt * 16) * 128 + ((kgA ^ rxA) << 4));
                LDSM4(ah[mt], cb + AH + off);
                LDSM4(al[mt], cb + AL + off);
            }
#pragma unroll
            for (int pr = 0; pr < 2; pr++) {
                uint32_t off = (uint32_t)((rowB0 + pr * 16) * 128 + ((kgB ^ rxB) << 4));
                LDSM4(bh[pr], cb + BH + off);
                LDSM4(bl[pr], cb + BL + off);
            }
#pragma unroll
            for (int mt = 0; mt < 2; mt++)
#pragma unroll
                for (int nt = 0; nt < 4; nt++) {
                    const int pr = nt >> 1, hi2 = (nt & 1) * 2;
                    MMA16816(acc[mt][nt], ah[mt], bh[pr][hi2], bh[pr][hi2 + 1]);
                    MMA16816(acc[mt][nt], al[mt], bh[pr][hi2], bh[pr][hi2 + 1]);
                    MMA16816(acc[mt][nt], ah[mt], bl[pr][hi2], bl[pr][hi2 + 1]);
                }
        }
        if (c < 3) __syncthreads();  // last chunk: no stage reuse follows
    }

    const int mrow = brow + wm * 32 + (lane >> 2);
    const int ncol0 = bcol + wn * 32 + (lane & 3) * 2;
#pragma unroll
    for (int mt = 0; mt < 2; mt++) {
#pragma unroll
        for (int half = 0; half < 2; half++) {
            int r = mrow + mt * 16 + half * 8;
            if (r < NN) {
#pragma unroll
                for (int nt = 0; nt < 4; nt++) {
                    int col = ncol0 + nt * 8;
                    int cb2 = (bcol == 0) ? col : col - 128;
                    float ox = acc[mt][nt][half * 2 + 0] + s_bias[cb2];
                    float oy = acc[mt][nt][half * 2 + 1] + s_bias[cb2 + 1];
                    if (mat == 0) {
                        *(float2*)(Cq + (size_t)r * DM + col) = make_float2(ox, oy);
                    } else {
                        __nv_bfloat16* Crow = ((mat == 1) ? Ck : Cv) + (size_t)r * DM;
                        *(__nv_bfloat162*)(Crow + col) = __floats2bfloat162_rn(ox, oy);
                    }
                }
            }
        }
    }
}

// ---------------- node-centric attention aggregation -------------------------
// warp per dst node; depth-1 prefetch (R10 config). 512 threads/block so the
// 8KB Eemb smem staging is amortized over 16 warps.
__global__ __launch_bounds__(512) void node_agg(
    const float* __restrict__ qf, const __nv_bfloat16* __restrict__ kb,
    const __nv_bfloat16* __restrict__ vb, const float* __restrict__ eembl,
    const int* __restrict__ batch, int last)
{
    __shared__ float se[8 * DM];  // Eemb for this layer, fp32 (8KB = 512 float4)
    int tid = threadIdx.x;
    ((float4*)se)[tid] = ((const float4*)eembl)[tid];
    __syncthreads();

    int lane = tid & 31;
    int n = blockIdx.x * 16 + (tid >> 5);
    if (n >= NN) return;
    int j0 = lane * 8;

    float qv[8];
    {
        float4 a = *(const float4*)(qf + (size_t)n * DM + j0);
        float4 b = *(const float4*)(qf + (size_t)n * DM + j0 + 4);
        qv[0] = a.x; qv[1] = a.y; qv[2] = a.z; qv[3] = a.w;
        qv[4] = b.x; qv[5] = b.y; qv[6] = b.z; qv[7] = b.w;
    }

    float acc[8] = {0.f, 0.f, 0.f, 0.f, 0.f, 0.f, 0.f, 0.f};
    float den = 0.f;

    int i = g_coff[n];
    const int e1 = i + g_ccnt[n];

    uint4 ku, vu;
    int t_cur = 0;
    if (i < e1) {
        int d = g_cdat[i];
        int s = d & 0xFFFF;
        t_cur = d >> 16;
        ku = *(const uint4*)(kb + (size_t)s * DM + j0);
        vu = *(const uint4*)(vb + (size_t)s * DM + j0);
    }

    while (i < e1) {
        uint4 kc = ku, vc = vu;
        int tc = t_cur;
        i++;
        if (i < e1) {
            int d = g_cdat[i];
            int s = d & 0xFFFF;
            t_cur = d >> 16;
            ku = *(const uint4*)(kb + (size_t)s * DM + j0);
            vu = *(const uint4*)(vb + (size_t)s * DM + j0);
        }

        float4 ea = *(const float4*)(se + tc * DM + j0);
        float4 eb = *(const float4*)(se + tc * DM + j0 + 4);
        const __nv_bfloat162* kp = (const __nv_bfloat162*)&kc;
        float2 k0 = __bfloat1622float2(kp[0]), k1 = __bfloat1622float2(kp[1]);
        float2 k2 = __bfloat1622float2(kp[2]), k3 = __bfloat1622float2(kp[3]);
        float sum = qv[0] * (k0.x + ea.x) + qv[1] * (k0.y + ea.y) +
                    qv[2] * (k1.x + ea.z) + qv[3] * (k1.y + ea.w) +
                    qv[4] * (k2.x + eb.x) + qv[5] * (k2.y + eb.y) +
                    qv[6] * (k3.x + eb.z) + qv[7] * (k3.y + eb.w);
        sum += __shfl_xor_sync(0xffffffffu, sum, 1);
        sum += __shfl_xor_sync(0xffffffffu, sum, 2);
        sum += __shfl_xor_sync(0xffffffffu, sum, 4);
        float ex = expf(sum * 0.125f);  // 1/sqrt(64); shift-free softmax
        den += ex;

        const __nv_bfloat162* vp = (const __nv_bfloat162*)&vc;
        float2 v0 = __bfloat1622float2(vp[0]), v1 = __bfloat1622float2(vp[1]);
        float2 v2 = __bfloat1622float2(vp[2]), v3 = __bfloat1622float2(vp[3]);
        acc[0] = fmaf(v0.x + ea.x, ex, acc[0]);
        acc[1] = fmaf(v0.y + ea.y, ex, acc[1]);
        acc[2] = fmaf(v1.x + ea.z, ex, acc[2]);
        acc[3] = fmaf(v1.y + ea.w, ex, acc[3]);
        acc[4] = fmaf(v2.x + eb.x, ex, acc[4]);
        acc[5] = fmaf(v2.y + eb.y, ex, acc[5]);
        acc[6] = fmaf(v3.x + eb.z, ex, acc[6]);
        acc[7] = fmaf(v3.y + eb.w, ex, acc[7]);
    }

    float inv = 1.0f / (den + 1e-16f);
    float o[8];
#pragma unroll
    for (int j = 0; j < 8; j++) {
        float a = acc[j] * inv;
        o[j] = (a > 0.f) ? a : expm1f(a);
    }

    if (last) {
        int b = batch[n];
        red_add_v4(g_gsum + (size_t)b * DM + j0,
                   make_float4(o[0], o[1], o[2], o[3]));
        red_add_v4(g_gsum + (size_t)b * DM + j0 + 4,
                   make_float4(o[4], o[5], o[6], o[7]));
        if (lane == 0) atomicAdd(&g_cnt[b], 1.0f);
    } else {
        unsigned short hb[8], lb[8];
#pragma unroll
        for (int j = 0; j < 8; j++) split_bf16(o[j], hb[j], lb[j]);
        uint4 ho, lu;
        ho.x = hb[0] | ((uint32_t)hb[1] << 16); ho.y = hb[2] | ((uint32_t)hb[3] << 16);
        ho.z = hb[4] | ((uint32_t)hb[5] << 16); ho.w = hb[6] | ((uint32_t)hb[7] << 16);
        lu.x = lb[0] | ((uint32_t)lb[1] << 16); lu.y = lb[2] | ((uint32_t)lb[3] << 16);
        lu.z = lb[4] | ((uint32_t)lb[5] << 16); lu.w = lb[6] | ((uint32_t)lb[7] << 16);
        ((uint4*)g_xhi)[n * 32 + lane] = ho;
        ((uint4*)g_xlo)[n * 32 + lane] = lu;
    }
}

// ---------------- tail: mean + GRU (h0=0) + fc ----------------
__global__ __launch_bounds__(64) void tail_kernel(
    const float* __restrict__ W_ih, const float* __restrict__ b_ih,
    const float* __restrict__ b_hh, const float* __restrict__ W_fc,
    const float* __restrict__ b_fc, float* __restrict__ out)
{
    __shared__ float gs[DM];
    __shared__ float hs[HD];
    int gph = blockIdx.x;
    int i = threadIdx.x;
    float c = fmaxf(g_cnt[gph], 1.0f);
#pragma unroll
    for (int r = 0; r < 4; r++) gs[i + r * 64] = g_gsum[gph * DM + i + r * 64] / c;
    __syncthreads();

    float ir = b_ih[i], iz = b_ih[64 + i], inn = b_ih[128 + i];
    const float* wr = W_ih + (size_t)i * 256;
    const float* wz = W_ih + (size_t)(64 + i) * 256;
    const float* wn = W_ih + (size_t)(128 + i) * 256;
#pragma unroll 8
    for (int j = 0; j < 256; j++) {
        float gv = gs[j];
        ir = fmaf(wr[j], gv, ir);
        iz = fmaf(wz[j], gv, iz);
        inn = fmaf(wn[j], gv, inn);
    }
    float r = 1.0f / (1.0f + expf(-(ir + b_hh[i])));
    float z = 1.0f / (1.0f + expf(-(iz + b_hh[64 + i])));
    float n = tanhf(inn + r * b_hh[128 + i]);
    hs[i] = (1.0f - z) * n;
    __syncthreads();
    if (i < 2) {
        float o = b_fc[i];
        for (int j = 0; j < HD; j++) o = fmaf(W_fc[i * HD + j], hs[j], o);
        out[gph * 2 + i] = o;
    }
}

// ---------------- host ----------------
extern "C" void kernel_launch(void* const* d_in, const int* in_sizes, int n_in,
                              void* d_out, int out_size)
{
    const float* x_in = (const float*)d_in[0];
    const int* ei = (const int*)d_in[1];
    const int* batch = (const int*)d_in[2];
    const int* et = (const int*)d_in[3];
    const float* Wq = (const float*)d_in[4];
    const float* bq = (const float*)d_in[5];
    const float* Wk = (const float*)d_in[6];
    const float* bk = (const float*)d_in[7];
    const float* Wv = (const float*)d_in[8];
    const float* bv = (const float*)d_in[9];
    const float* Ee = (const float*)d_in[10];
    const float* W_ih = (const float*)d_in[11];
    const float* b_ih = (const float*)d_in[12];
    const float* b_hh = (const float*)d_in[14];
    const float* W_fc = (const float*)d_in[15];
    const float* b_fc = (const float*)d_in[16];
    float* out = (float*)d_out;

    const int* src = ei;
    const int* dst = ei + EE;

    void *p_qf, *p_kb, *p_vb, *p_xhi, *p_xlo, *p_whi, *p_wlo;
    cudaGetSymbolAddress(&p_qf, g_qf);
    cudaGetSymbolAddress(&p_kb, g_kb);
    cudaGetSymbolAddress(&p_vb, g_vb);
    cudaGetSymbolAddress(&p_xhi, g_xhi);
    cudaGetSymbolAddress(&p_xlo, g_xlo);
    cudaGetSymbolAddress(&p_whi, g_whi);
    cudaGetSymbolAddress(&p_wlo, g_wlo);

    const int SMEM_GEMM = 131072;  // 2 stages x 64KB (R10 config)
    cudaFuncSetAttribute(gemm_tc, cudaFuncAttributeMaxDynamicSharedMemorySize, SMEM_GEMM);

    dim3 gemm_grid(6, (NN + 127) / 128);

    // Launch order places gemm_tc as the 4th kernel (ncu -s 5 -c 1 captures it).
    conv_w<<<dim3(8, 8, 9), dim3(32, 8)>>>(Wq, Wk, Wv,
                                           (__nv_bfloat16*)p_whi, (__nv_bfloat16*)p_wlo);
    conv_x<<<(NN * DM / 8 + 255) / 256, 256>>>(x_in, (__nv_bfloat16*)p_xhi,
                                               (__nv_bfloat16*)p_xlo);
    zero_bufs<<<(NN + 255) / 256, 256>>>();

    gemm_tc<<<gemm_grid, 512, SMEM_GEMM>>>(
        (const __nv_bfloat16*)p_xhi, (const __nv_bfloat16*)p_xlo,
        (const __nv_bfloat16*)p_whi, (const __nv_bfloat16*)p_wlo,
        bq, bk, bv,
        (float*)p_qf, (__nv_bfloat16*)p_kb, (__nv_bfloat16*)p_vb);

    csr_hist<<<(EE + 255) / 256, 256>>>(dst);
    csr_off<<<(NN + 255) / 256, 256>>>();
    csr_scatter<<<(EE + 255) / 256, 256>>>(src, dst, et);

    for (int l = 0; l < NL; l++) {
        if (l > 0) {
            gemm_tc<<<gemm_grid, 512, SMEM_GEMM>>>(
                (const __nv_bfloat16*)p_xhi, (const __nv_bfloat16*)p_xlo,
                (const __nv_bfloat16*)p_whi + (size_t)l * 3 * DM * DM,
                (const __nv_bfloat16*)p_wlo + (size_t)l * 3 * DM * DM,
                bq + l * DM, bk + l * DM, bv + l * DM,
                (float*)p_qf, (__nv_bfloat16*)p_kb, (__nv_bfloat16*)p_vb);
        }
        node_agg<<<(NN + 15) / 16, 512>>>(
            (const float*)p_qf, (const __nv_bfloat16*)p_kb,
            (const __nv_bfloat16*)p_vb, Ee + (size_t)l * 8 * DM,
            batch, (l == NL - 1) ? 1 : 0);
    }

    tail_kernel<<<NG, 64>>>(W_ih, b_ih, b_hh, W_fc, b_fc, out);
}

// round 17
// speedup vs baseline: 1.0469x; 1.0469x over previous
#include <cuda_runtime.h>
#include <cuda_bf16.h>
#include <math.h>
#include <stdint.h>

#define NN 30000
#define EE 240000
#define DM 256
#define NH 4
#define HD 64
#define NG 64
#define NL 3

// ---------------- scratch (static device globals; no allocs) ----------------
__device__ float g_qf[NN * DM];       // q in fp32
__device__ float g_gsum[NG * DM];
__device__ float g_cnt[NG];
__device__ int g_total;
// bf16 operands / activations
__device__ __nv_bfloat16 g_kb[NN * DM];
__device__ __nv_bfloat16 g_vb[NN * DM];
__device__ __nv_bfloat16 g_xhi[NN * DM];
__device__ __nv_bfloat16 g_xlo[NN * DM];
__device__ __nv_bfloat16 g_whi[9 * DM * DM];  // [l*3+mat][n][k] K-major
__device__ __nv_bfloat16 g_wlo[9 * DM * DM];
// CSR by destination node (offsets NOT monotone in n; segment = [off, off+cnt))
__device__ int g_ccnt[NN];
__device__ int g_coff[NN];
__device__ int g_ccur[NN];
__device__ int g_cdat[EE];            // src | (et << 16)

// ---------------- helpers ----------------
__device__ __forceinline__ void red_add_v4(float* p, float4 v) {
    asm volatile("red.global.add.v4.f32 [%0], {%1,%2,%3,%4};"
                 :: "l"(p), "f"(v.x), "f"(v.y), "f"(v.z), "f"(v.w) : "memory");
}
__device__ __forceinline__ uint32_t smem_u32(const void* p) {
    uint32_t a;
    asm("{ .reg .u64 t; cvta.to.shared.u64 t, %1; cvt.u32.u64 %0, t; }"
        : "=r"(a) : "l"(p));
    return a;
}

#define LDSM4(r, addr) \
    asm volatile("ldmatrix.sync.aligned.m8n8.x4.shared.b16 {%0,%1,%2,%3}, [%4];" \
                 : "=r"((r)[0]), "=r"((r)[1]), "=r"((r)[2]), "=r"((r)[3]) \
                 : "r"(addr))

#define MMA16816(c, a, b0, b1) \
    asm volatile("mma.sync.aligned.m16n8k16.row.col.f32.bf16.bf16.f32 " \
                 "{%0,%1,%2,%3},{%4,%5,%6,%7},{%8,%9},{%0,%1,%2,%3};" \
                 : "+f"((c)[0]), "+f"((c)[1]), "+f"((c)[2]), "+f"((c)[3]) \
                 : "r"((a)[0]), "r"((a)[1]), "r"((a)[2]), "r"((a)[3]), \
                   "r"(b0), "r"(b1))

// .cg: bypass L1 — async fills are single-use; keep L1TEX for ldmatrix
#define CP16(smaddr, gptr) \
    asm volatile("cp.async.cg.shared.global [%0], [%1], 16;" \
                 :: "r"(smaddr), "l"(gptr) : "memory")
#define CPCOMMIT() asm volatile("cp.async.commit_group;" ::: "memory")
#define CPWAIT1() asm volatile("cp.async.wait_group 1;" ::: "memory")
#define CPWAIT0() asm volatile("cp.async.wait_group 0;" ::: "memory")

__device__ __forceinline__ void split_bf16(float v, unsigned short& h, unsigned short& l) {
    __nv_bfloat16 hb = __float2bfloat16(v);
    h = __bfloat16_as_ushort(hb);
    l = __bfloat16_as_ushort(__float2bfloat16(v - __bfloat162float(hb)));
}

// ---------------- zero all small buffers in one launch ----------------
__global__ __launch_bounds__(256) void zero_bufs()
{
    int i = blockIdx.x * blockDim.x + threadIdx.x;
    if (i < NN) g_ccnt[i] = 0;
    if (i < NG * DM) g_gsum[i] = 0.f;
    if (i < NG) g_cnt[i] = 0.f;
    if (i == 0) g_total = 0;
}

// ---------------- CSR construction ----------------
__global__ __launch_bounds__(256) void csr_hist(const int* __restrict__ dst)
{
    int e = blockIdx.x * blockDim.x + threadIdx.x;
    if (e < EE) atomicAdd(&g_ccnt[dst[e]], 1);
}

__global__ __launch_bounds__(256) void csr_off()
{
    int n = blockIdx.x * blockDim.x + threadIdx.x;
    if (n >= NN) return;
    int c = g_ccnt[n];
    int p = atomicAdd(&g_total, c);
    g_coff[n] = p;
    g_ccur[n] = p;
}

__global__ __launch_bounds__(256) void csr_scatter(
    const int* __restrict__ src, const int* __restrict__ dst,
    const int* __restrict__ et)
{
    int e = blockIdx.x * blockDim.x + threadIdx.x;
    if (e >= EE) return;
    int p = atomicAdd(&g_ccur[dst[e]], 1);
    g_cdat[p] = src[e] | (et[e] << 16);
}

// ---------------- bf16 split conversion: x -> hi/lo (layer 0 only) ----------
__global__ __launch_bounds__(256) void conv_x(
    const float* __restrict__ x, __nv_bfloat16* __restrict__ hi,
    __nv_bfloat16* __restrict__ lo)
{
    int i = blockIdx.x * blockDim.x + threadIdx.x;
    if (i >= NN * DM / 8) return;
    const float4* x4 = (const float4*)x;
    float4 a = x4[2 * i], b = x4[2 * i + 1];
    float v[8] = {a.x, a.y, a.z, a.w, b.x, b.y, b.z, b.w};
    unsigned short hb[8], lb[8];
#pragma unroll
    for (int j = 0; j < 8; j++) split_bf16(v[j], hb[j], lb[j]);
    uint4 ho, lu;
    ho.x = hb[0] | ((uint32_t)hb[1] << 16); ho.y = hb[2] | ((uint32_t)hb[3] << 16);
    ho.z = hb[4] | ((uint32_t)hb[5] << 16); ho.w = hb[6] | ((uint32_t)hb[7] << 16);
    lu.x = lb[0] | ((uint32_t)lb[1] << 16); lu.y = lb[2] | ((uint32_t)lb[3] << 16);
    lu.z = lb[4] | ((uint32_t)lb[5] << 16); lu.w = lb[6] | ((uint32_t)lb[7] << 16);
    ((uint4*)hi)[i] = ho;
    ((uint4*)lo)[i] = lu;
}

// ---------------- W transpose + split ----------------
__global__ void conv_w(const float* __restrict__ Wq, const float* __restrict__ Wk,
                       const float* __restrict__ Wv,
                       __nv_bfloat16* __restrict__ whi, __nv_bfloat16* __restrict__ wlo)
{
    __shared__ float t[32][33];
    int m3 = blockIdx.z, l = m3 / 3, mat = m3 % 3;
    const float* W = ((mat == 0) ? Wq : (mat == 1) ? Wk : Wv) + (size_t)l * DM * DM;
    int n0 = blockIdx.x * 32, k0 = blockIdx.y * 32;
#pragma unroll
    for (int i = 0; i < 4; i++)
        t[threadIdx.y + i * 8][threadIdx.x] =
            W[(size_t)(k0 + threadIdx.y + i * 8) * DM + n0 + threadIdx.x];
    __syncthreads();
#pragma unroll
    for (int i = 0; i < 4; i++) {
        int n = n0 + threadIdx.y + i * 8;
        int k = k0 + threadIdx.x;
        float v = t[threadIdx.x][threadIdx.y + i * 8];
        unsigned short h, lo16;
        split_bf16(v, h, lo16);
        size_t o = (size_t)m3 * DM * DM + (size_t)n * DM + k;
        whi[o] = __ushort_as_bfloat16(h);
        wlo[o] = __ushort_as_bfloat16(lo16);
    }
}

// ---------------- HMMA split GEMM, cp.async 2-stage + B-frag pipeline --------
// grid (6, 235). 512 threads. CTA tile 128x128, K=256 in 4 chunks of 64.
// Full 3-term split everywhere (R11 lesson). R16 profile: tensor 50.7%,
// L1 63% -> .cg fills (L1 bypass) + cross-ks B-fragment double buffering
// to keep the tensor pipe fed through LDSM latency.
__global__ __launch_bounds__(512, 1) void gemm_tc(
    const __nv_bfloat16* __restrict__ xhi, const __nv_bfloat16* __restrict__ xlo,
    const __nv_bfloat16* __restrict__ whi, const __nv_bfloat16* __restrict__ wlo,
    const float* __restrict__ bq, const float* __restrict__ bk,
    const float* __restrict__ bv,
    float* __restrict__ Cq, __nv_bfloat16* __restrict__ Ck,
    __nv_bfloat16* __restrict__ Cv)
{
    extern __shared__ char sm[];
    __shared__ float s_bias[128];
    const uint32_t sbase = smem_u32(sm);
    const uint32_t AH = 0, AL = 16384, BH = 32768, BL = 49152;
    const uint32_t STAGE = 65536;

    const int tid = threadIdx.x;
    const int warp = tid >> 5, lane = tid & 31;
    const int wm = warp & 3, wn = warp >> 2;
    const int mat = blockIdx.x >> 1;
    const int bcol = (blockIdx.x & 1) * 128;
    const int brow = blockIdx.y * 128;

    const float* bias = (mat == 0) ? bq : (mat == 1) ? bk : bv;
    if (tid < 128) s_bias[tid] = bias[bcol + tid];

    const int lrow = tid >> 2;
    const int lq = tid & 3;
    const int arow = min(brow + lrow, NN - 1);
    const __nv_bfloat16* pAh = xhi + (size_t)arow * DM;
    const __nv_bfloat16* pAl = xlo + (size_t)arow * DM;
    const __nv_bfloat16* pBh = whi + (size_t)mat * DM * DM + (size_t)(bcol + lrow) * DM;
    const __nv_bfloat16* pBl = wlo + (size_t)mat * DM * DM + (size_t)(bcol + lrow) * DM;
    const int lrx = lrow & 7;

    const int sA_m = ((lane >> 3) & 1) * 8 + (lane & 7);
    const int sA_k = lane >> 4;
    const int sB_n = (lane >> 4) * 8 + (lane & 7);
    const int sB_k = (lane >> 3) & 1;
    const int rowA0 = wm * 32 + sA_m;
    const int rowB0 = wn * 32 + sB_n;
    const int rxA = sA_m & 7;
    const int rxB = sB_n & 7;

    float acc[2][4][4];
#pragma unroll
    for (int mt = 0; mt < 2; mt++)
#pragma unroll
        for (int nt = 0; nt < 4; nt++)
#pragma unroll
            for (int j = 0; j < 4; j++) acc[mt][nt][j] = 0.f;

#define ISSUE_CHUNK(chunk, stg)                                                  \
    {                                                                            \
        _Pragma("unroll")                                                        \
        for (int j = 0; j < 2; j++) {                                            \
            int g = lq + j * 4;                                                  \
            int elem = (chunk) * 64 + g * 8;                                     \
            uint32_t sw = (uint32_t)(lrow * 128 + ((g ^ lrx) << 4));             \
            CP16((stg) + AH + sw, pAh + elem);                                   \
            CP16((stg) + AL + sw, pAl + elem);                                   \
            CP16((stg) + BH + sw, pBh + elem);                                   \
            CP16((stg) + BL + sw, pBl + elem);                                   \
        }                                                                        \
        CPCOMMIT();                                                              \
    }

    ISSUE_CHUNK(0, sbase);

#pragma unroll
    for (int c = 0; c < 4; c++) {
        const uint32_t cb = sbase + (uint32_t)(c & 1) * STAGE;
        if (c < 3) {
            ISSUE_CHUNK(c + 1, sbase + (uint32_t)((c + 1) & 1) * STAGE);
            CPWAIT1();
        } else {
            CPWAIT0();
        }
        __syncthreads();

        // B-fragment double buffer across ks
        uint32_t bh[2][2][4], bl[2][2][4];
#pragma unroll
        for (int pr = 0; pr < 2; pr++) {
            uint32_t off = (uint32_t)((rowB0 + pr * 16) * 128 + ((sB_k ^ rxB) << 4));
            LDSM4(bh[0][pr], cb + BH + off);
            LDSM4(bl[0][pr], cb + BL + off);
        }

#pragma unroll
        for (int ks = 0; ks < 4; ks++) {
            const int cur = ks & 1, nxt = cur ^ 1;
            const int kgA = ks * 2 + sA_k;
            uint32_t ah[2][4], al[2][4];
#pragma unroll
            for (int mt = 0; mt < 2; mt++) {
                uint32_t off = (uint32_t)((rowA0 + mt * 16) * 128 + ((kgA ^ rxA) << 4));
                LDSM4(ah[mt], cb + AH + off);
                LDSM4(al[mt], cb + AL + off);
            }
            if (ks < 3) {
                const int kgB = (ks + 1) * 2 + sB_k;
#pragma unroll
                for (int pr = 0; pr < 2; pr++) {
                    uint32_t off = (uint32_t)((rowB0 + pr * 16) * 128 + ((kgB ^ rxB) << 4));
                    LDSM4(bh[nxt][pr], cb + BH + off);
                    LDSM4(bl[nxt][pr], cb + BL + off);
                }
            }
#pragma unroll
            for (int mt = 0; mt < 2; mt++)
#pragma unroll
                for (int nt = 0; nt < 4; nt++) {
                    const int pr = nt >> 1, hi2 = (nt & 1) * 2;
                    MMA16816(acc[mt][nt], ah[mt], bh[cur][pr][hi2], bh[cur][pr][hi2 + 1]);
                    MMA16816(acc[mt][nt], al[mt], bh[cur][pr][hi2], bh[cur][pr][hi2 + 1]);
                    MMA16816(acc[mt][nt], ah[mt], bl[cur][pr][hi2], bl[cur][pr][hi2 + 1]);
                }
        }
        if (c < 3) __syncthreads();
    }

    const int mrow = brow + wm * 32 + (lane >> 2);
    const int ncol0 = bcol + wn * 32 + (lane & 3) * 2;
#pragma unroll
    for (int mt = 0; mt < 2; mt++) {
#pragma unroll
        for (int half = 0; half < 2; half++) {
            int r = mrow + mt * 16 + half * 8;
            if (r < NN) {
#pragma unroll
                for (int nt = 0; nt < 4; nt++) {
                    int col = ncol0 + nt * 8;
                    int cb2 = (bcol == 0) ? col : col - 128;
                    float ox = acc[mt][nt][half * 2 + 0] + s_bias[cb2];
                    float oy = acc[mt][nt][half * 2 + 1] + s_bias[cb2 + 1];
                    if (mat == 0) {
                        *(float2*)(Cq + (size_t)r * DM + col) = make_float2(ox, oy);
                    } else {
                        __nv_bfloat16* Crow = ((mat == 1) ? Ck : Cv) + (size_t)r * DM;
                        *(__nv_bfloat162*)(Crow + col) = __floats2bfloat162_rn(ox, oy);
                    }
                }
            }
        }
    }
}

// ---------------- node-centric attention aggregation -------------------------
// warp per dst node; depth-1 prefetch; 512 threads/block (R15 config).
__global__ __launch_bounds__(512) void node_agg(
    const float* __restrict__ qf, const __nv_bfloat16* __restrict__ kb,
    const __nv_bfloat16* __restrict__ vb, const float* __restrict__ eembl,
    const int* __restrict__ batch, int last)
{
    __shared__ float se[8 * DM];
    int tid = threadIdx.x;
    ((float4*)se)[tid] = ((const float4*)eembl)[tid];
    __syncthreads();

    int lane = tid & 31;
    int n = blockIdx.x * 16 + (tid >> 5);
    if (n >= NN) return;
    int j0 = lane * 8;

    float qv[8];
    {
        float4 a = *(const float4*)(qf + (size_t)n * DM + j0);
        float4 b = *(const float4*)(qf + (size_t)n * DM + j0 + 4);
        qv[0] = a.x; qv[1] = a.y; qv[2] = a.z; qv[3] = a.w;
        qv[4] = b.x; qv[5] = b.y; qv[6] = b.z; qv[7] = b.w;
    }

    float acc[8] = {0.f, 0.f, 0.f, 0.f, 0.f, 0.f, 0.f, 0.f};
    float den = 0.f;

    int i = g_coff[n];
    const int e1 = i + g_ccnt[n];

    uint4 ku, vu;
    int t_cur = 0;
    if (i < e1) {
        int d = g_cdat[i];
        int s = d & 0xFFFF;
        t_cur = d >> 16;
        ku = *(const uint4*)(kb + (size_t)s * DM + j0);
        vu = *(const uint4*)(vb + (size_t)s * DM + j0);
    }

    while (i < e1) {
        uint4 kc = ku, vc = vu;
        int tc = t_cur;
        i++;
        if (i < e1) {
            int d = g_cdat[i];
            int s = d & 0xFFFF;
            t_cur = d >> 16;
            ku = *(const uint4*)(kb + (size_t)s * DM + j0);
            vu = *(const uint4*)(vb + (size_t)s * DM + j0);
        }

        float4 ea = *(const float4*)(se + tc * DM + j0);
        float4 eb = *(const float4*)(se + tc * DM + j0 + 4);
        const __nv_bfloat162* kp = (const __nv_bfloat162*)&kc;
        float2 k0 = __bfloat1622float2(kp[0]), k1 = __bfloat1622float2(kp[1]);
        float2 k2 = __bfloat1622float2(kp[2]), k3 = __bfloat1622float2(kp[3]);
        float sum = qv[0] * (k0.x + ea.x) + qv[1] * (k0.y + ea.y) +
                    qv[2] * (k1.x + ea.z) + qv[3] * (k1.y + ea.w) +
                    qv[4] * (k2.x + eb.x) + qv[5] * (k2.y + eb.y) +
                    qv[6] * (k3.x + eb.z) + qv[7] * (k3.y + eb.w);
        sum += __shfl_xor_sync(0xffffffffu, sum, 1);
        sum += __shfl_xor_sync(0xffffffffu, sum, 2);
        sum += __shfl_xor_sync(0xffffffffu, sum, 4);
        float ex = expf(sum * 0.125f);  // 1/sqrt(64); shift-free softmax
        den += ex;

        const __nv_bfloat162* vp = (const __nv_bfloat162*)&vc;
        float2 v0 = __bfloat1622float2(vp[0]), v1 = __bfloat1622float2(vp[1]);
        float2 v2 = __bfloat1622float2(vp[2]), v3 = __bfloat1622float2(vp[3]);
        acc[0] = fmaf(v0.x + ea.x, ex, acc[0]);
        acc[1] = fmaf(v0.y + ea.y, ex, acc[1]);
        acc[2] = fmaf(v1.x + ea.z, ex, acc[2]);
        acc[3] = fmaf(v1.y + ea.w, ex, acc[3]);
        acc[4] = fmaf(v2.x + eb.x, ex, acc[4]);
        acc[5] = fmaf(v2.y + eb.y, ex, acc[5]);
        acc[6] = fmaf(v3.x + eb.z, ex, acc[6]);
        acc[7] = fmaf(v3.y + eb.w, ex, acc[7]);
    }

    float inv = 1.0f / (den + 1e-16f);
    float o[8];
#pragma unroll
    for (int j = 0; j < 8; j++) {
        float a = acc[j] * inv;
        o[j] = (a > 0.f) ? a : expm1f(a);
    }

    if (last) {
        int b = batch[n];
        red_add_v4(g_gsum + (size_t)b * DM + j0,
                   make_float4(o[0], o[1], o[2], o[3]));
        red_add_v4(g_gsum + (size_t)b * DM + j0 + 4,
                   make_float4(o[4], o[5], o[6], o[7]));
        if (lane == 0) atomicAdd(&g_cnt[b], 1.0f);
    } else {
        unsigned short hb[8], lb[8];
#pragma unroll
        for (int j = 0; j < 8; j++) split_bf16(o[j], hb[j], lb[j]);
        uint4 ho, lu;
        ho.x = hb[0] | ((uint32_t)hb[1] << 16); ho.y = hb[2] | ((uint32_t)hb[3] << 16);
        ho.z = hb[4] | ((uint32_t)hb[5] << 16); ho.w = hb[6] | ((uint32_t)hb[7] << 16);
        lu.x = lb[0] | ((uint32_t)lb[1] << 16); lu.y = lb[2] | ((uint32_t)lb[3] << 16);
        lu.z = lb[4] | ((uint32_t)lb[5] << 16); lu.w = lb[6] | ((uint32_t)lb[7] << 16);
        ((uint4*)g_xhi)[n * 32 + lane] = ho;
        ((uint4*)g_xlo)[n * 32 + lane] = lu;
    }
}

// ---------------- tail: mean + GRU (h0=0) + fc ----------------
__global__ __launch_bounds__(64) void tail_kernel(
    const float* __restrict__ W_ih, const float* __restrict__ b_ih,
    const float* __restrict__ b_hh, const float* __restrict__ W_fc,
    const float* __restrict__ b_fc, float* __restrict__ out)
{
    __shared__ float gs[DM];
    __shared__ float hs[HD];
    int gph = blockIdx.x;
    int i = threadIdx.x;
    float c = fmaxf(g_cnt[gph], 1.0f);
#pragma unroll
    for (int r = 0; r < 4; r++) gs[i + r * 64] = g_gsum[gph * DM + i + r * 64] / c;
    __syncthreads();

    float ir = b_ih[i], iz = b_ih[64 + i], inn = b_ih[128 + i];
    const float* wr = W_ih + (size_t)i * 256;
    const float* wz = W_ih + (size_t)(64 + i) * 256;
    const float* wn = W_ih + (size_t)(128 + i) * 256;
#pragma unroll 8
    for (int j = 0; j < 256; j++) {
        float gv = gs[j];
        ir = fmaf(wr[j], gv, ir);
        iz = fmaf(wz[j], gv, iz);
        inn = fmaf(wn[j], gv, inn);
    }
    float r = 1.0f / (1.0f + expf(-(ir + b_hh[i])));
    float z = 1.0f / (1.0f + expf(-(iz + b_hh[64 + i])));
    float n = tanhf(inn + r * b_hh[128 + i]);
    hs[i] = (1.0f - z) * n;
    __syncthreads();
    if (i < 2) {
        float o = b_fc[i];
        for (int j = 0; j < HD; j++) o = fmaf(W_fc[i * HD + j], hs[j], o);
        out[gph * 2 + i] = o;
    }
}

// ---------------- host ----------------
extern "C" void kernel_launch(void* const* d_in, const int* in_sizes, int n_in,
                              void* d_out, int out_size)
{
    const float* x_in = (const float*)d_in[0];
    const int* ei = (const int*)d_in[1];
    const int* batch = (const int*)d_in[2];
    const int* et = (const int*)d_in[3];
    const float* Wq = (const float*)d_in[4];
    const float* bq = (const float*)d_in[5];
    const float* Wk = (const float*)d_in[6];
    const float* bk = (const float*)d_in[7];
    const float* Wv = (const float*)d_in[8];
    const float* bv = (const float*)d_in[9];
    const float* Ee = (const float*)d_in[10];
    const float* W_ih = (const float*)d_in[11];
    const float* b_ih = (const float*)d_in[12];
    const float* b_hh = (const float*)d_in[14];
    const float* W_fc = (const float*)d_in[15];
    const float* b_fc = (const float*)d_in[16];
    float* out = (float*)d_out;

    const int* src = ei;
    const int* dst = ei + EE;

    void *p_qf, *p_kb, *p_vb, *p_xhi, *p_xlo, *p_whi, *p_wlo;
    cudaGetSymbolAddress(&p_qf, g_qf);
    cudaGetSymbolAddress(&p_kb, g_kb);
    cudaGetSymbolAddress(&p_vb, g_vb);
    cudaGetSymbolAddress(&p_xhi, g_xhi);
    cudaGetSymbolAddress(&p_xlo, g_xlo);
    cudaGetSymbolAddress(&p_whi, g_whi);
    cudaGetSymbolAddress(&p_wlo, g_wlo);

    const int SMEM_GEMM = 131072;  // 2 stages x 64KB
    cudaFuncSetAttribute(gemm_tc, cudaFuncAttributeMaxDynamicSharedMemorySize, SMEM_GEMM);

    dim3 gemm_grid(6, (NN + 127) / 128);

    // Launch order places gemm_tc as the 4th kernel (ncu -s 5 -c 1 captures it).
    conv_w<<<dim3(8, 8, 9), dim3(32, 8)>>>(Wq, Wk, Wv,
                                           (__nv_bfloat16*)p_whi, (__nv_bfloat16*)p_wlo);
    conv_x<<<(NN * DM / 8 + 255) / 256, 256>>>(x_in, (__nv_bfloat16*)p_xhi,
                                               (__nv_bfloat16*)p_xlo);
    zero_bufs<<<(NN + 255) / 256, 256>>>();

    gemm_tc<<<gemm_grid, 512, SMEM_GEMM>>>(
        (const __nv_bfloat16*)p_xhi, (const __nv_bfloat16*)p_xlo,
        (const __nv_bfloat16*)p_whi, (const __nv_bfloat16*)p_wlo,
        bq, bk, bv,
        (float*)p_qf, (__nv_bfloat16*)p_kb, (__nv_bfloat16*)p_vb);

    csr_hist<<<(EE + 255) / 256, 256>>>(dst);
    csr_off<<<(NN + 255) / 256, 256>>>();
    csr_scatter<<<(EE + 255) / 256, 256>>>(src, dst, et);

    for (int l = 0; l < NL; l++) {
        if (l > 0) {
            gemm_tc<<<gemm_grid, 512, SMEM_GEMM>>>(
                (const __nv_bfloat16*)p_xhi, (const __nv_bfloat16*)p_xlo,
                (const __nv_bfloat16*)p_whi + (size_t)l * 3 * DM * DM,
                (const __nv_bfloat16*)p_wlo + (size_t)l * 3 * DM * DM,
                bq + l * DM, bk + l * DM, bv + l * DM,
                (float*)p_qf, (__nv_bfloat16*)p_kb, (__nv_bfloat16*)p_vb);
        }
        node_agg<<<(NN + 15) / 16, 512>>>(
            (const float*)p_qf, (const __nv_bfloat16*)p_kb,
            (const __nv_bfloat16*)p_vb, Ee + (size_t)l * 8 * DM,
            batch, (l == NL - 1) ? 1 : 0);
    }

    tail_kernel<<<NG, 64>>>(W_ih, b_ih, b_hh, W_fc, b_fc, out);
}